// round 1
// baseline (speedup 1.0000x reference)
#include <cuda_runtime.h>
#include <math.h>

// Problem dims
#define B_  16
#define C_  256
#define H_  128
#define W_  128
#define HW  (H_ * W_)         // 16384
#define HW4 (HW / 4)          // 4096 float4 per plane

// Device scratch (no allocation allowed)
__device__ float g_m[B_ * HW];        // channel-mean map [b][h][w]
__device__ float g_cf[B_ * C_];       // sigmoid gate [b][c]
__device__ float g_Pt[B_ * HW];       // (C*m) stored transposed: [b][w][u]
__device__ float g_Qt[B_ * HW];       // (S*m) stored transposed: [b][w][u]
__device__ float g_sf[B_ * HW];       // sf [b][h][w]

// ---------------------------------------------------------------------------
// Kernel 1: m[b,h,w] = (1/256) * sum_c x[b,c,h,w]      (float4 over w)
// 65536 threads, each sums 256 strided float4 loads (stride = one plane).
// ---------------------------------------------------------------------------
__global__ void mean_kernel(const float4* __restrict__ x) {
    int t = blockIdx.x * 256 + threadIdx.x;            // 0 .. 65535
    int b = t >> 12;                                    // /4096
    int pos = t & 4095;
    const float4* p = x + (size_t)b * C_ * HW4 + pos;
    float4 acc = make_float4(0.f, 0.f, 0.f, 0.f);
#pragma unroll 8
    for (int c = 0; c < C_; ++c) {
        float4 v = p[(size_t)c * HW4];
        acc.x += v.x; acc.y += v.y; acc.z += v.z; acc.w += v.w;
    }
    const float s = 1.0f / 256.0f;
    acc.x *= s; acc.y *= s; acc.z *= s; acc.w *= s;
    ((float4*)g_m)[t] = acc;
}

// ---------------------------------------------------------------------------
// Kernel 2: cf[b,c] = sigmoid( sum_k x[b,k,0,0] * W[c,k] + bias[c] )
// One block per batch; x[b,:,0,0] staged in shared.
// ---------------------------------------------------------------------------
__global__ void cf_kernel(const float* __restrict__ x,
                          const float* __restrict__ Wm,
                          const float* __restrict__ bias) {
    __shared__ __align__(16) float xs[C_];
    int b = blockIdx.x;
    int c = threadIdx.x;
    xs[c] = x[((size_t)(b * C_ + c)) * HW];   // x[b,c,0,0]
    __syncthreads();

    float acc = bias[c];
    const float4* wr = (const float4*)(Wm + (size_t)c * C_);
    const float4* xv = (const float4*)xs;
#pragma unroll 8
    for (int k = 0; k < C_ / 4; ++k) {
        float4 w4 = wr[k];
        float4 x4 = xv[k];
        acc += w4.x * x4.x + w4.y * x4.y + w4.z * x4.z + w4.w * x4.w;
    }
    g_cf[b * C_ + c] = 1.0f / (1.0f + expf(-acc));
}

// ---------------------------------------------------------------------------
// DFT stage kernels. Both have the pattern:
//   out[r][j] = sum_k tabC[(r*k)&127] * inA[k][j]  (stage2 adds -tabS*inB)
// tab index maintained incrementally: idx_{k+1} = (idx_k + r) & 127.
// Block: 256 threads = 128 rows (r) x 2 col-groups x 8 cols; col-tile = 16.
// Grid: (8 col-tiles, 16 batches). Output written TRANSPOSED with coalesced
// stores so the consumer always reads row-major (K-major) input.
// ---------------------------------------------------------------------------

// Stage 1: P[u][w] = sum_h C[u,h] m[h][w]; Q likewise with S.
// Writes Pt[w][u], Qt[w][u].
__global__ void dft_stage1(void) {
    __shared__ float ct[128], st[128];
    __shared__ __align__(16) float ms[128 * 16];   // m tile [h][16 w]

    int b  = blockIdx.y;
    int wt = blockIdx.x;           // w-tile (16 wide)
    int tid = threadIdx.x;

    if (tid < 128) {
        float s, c;
        sincospif((float)tid * (1.0f / 64.0f), &s, &c);  // angle 2*pi*tid/128
        ct[tid] = c; st[tid] = s;
    }
    // load m[:, wt*16 .. wt*16+15]
    const float* mb = g_m + (size_t)b * HW;
#pragma unroll
    for (int i = 0; i < 8; ++i) {
        int idx = tid + i * 256;           // 0..2047
        int h = idx >> 4, wl = idx & 15;
        ms[idx] = mb[h * W_ + wt * 16 + wl];
    }
    __syncthreads();

    int u  = tid & 127;
    int wg = tid >> 7;                      // 0..1, 8 w each
    const float4* ms4 = (const float4*)ms;

    float accP[8] = {0,0,0,0,0,0,0,0};
    float accQ[8] = {0,0,0,0,0,0,0,0};
    int idx = 0;
#pragma unroll 4
    for (int h = 0; h < 128; ++h) {
        float cu = ct[idx], su = st[idx];
        idx = (idx + u) & 127;
        float4 m0 = ms4[h * 4 + wg * 2 + 0];
        float4 m1 = ms4[h * 4 + wg * 2 + 1];
        accP[0] += cu * m0.x; accQ[0] += su * m0.x;
        accP[1] += cu * m0.y; accQ[1] += su * m0.y;
        accP[2] += cu * m0.z; accQ[2] += su * m0.z;
        accP[3] += cu * m0.w; accQ[3] += su * m0.w;
        accP[4] += cu * m1.x; accQ[4] += su * m1.x;
        accP[5] += cu * m1.y; accQ[5] += su * m1.y;
        accP[6] += cu * m1.z; accQ[6] += su * m1.z;
        accP[7] += cu * m1.w; accQ[7] += su * m1.w;
    }
    // transposed store: Pt[b][w][u], w = wt*16 + wg*8 + j  (coalesced in u)
    size_t base = (size_t)b * HW;
#pragma unroll
    for (int j = 0; j < 8; ++j) {
        int w = wt * 16 + wg * 8 + j;
        g_Pt[base + w * 128 + u] = accP[j];
        g_Qt[base + w * 128 + u] = accQ[j];
    }
}

// Stage 2: sf[u][v] = sum_w P[u][w]*C[v,w] - Q[u][w]*S[v,w]
// Computed as sfT[v][u] = sum_w C[v,w]*Pt[w][u] - S[v,w]*Qt[w][u],
// stored back transposed into g_sf[b][u][v] (coalesced in v).
__global__ void dft_stage2(void) {
    __shared__ float ct[128], st[128];
    __shared__ __align__(16) float ps[128 * 16];
    __shared__ __align__(16) float qs[128 * 16];

    int b  = blockIdx.y;
    int ut = blockIdx.x;            // u-tile (16 wide)
    int tid = threadIdx.x;

    if (tid < 128) {
        float s, c;
        sincospif((float)tid * (1.0f / 64.0f), &s, &c);
        ct[tid] = c; st[tid] = s;
    }
    const float* pb = g_Pt + (size_t)b * HW;
    const float* qb = g_Qt + (size_t)b * HW;
#pragma unroll
    for (int i = 0; i < 8; ++i) {
        int idx = tid + i * 256;
        int w = idx >> 4, ul = idx & 15;
        ps[idx] = pb[w * 128 + ut * 16 + ul];
        qs[idx] = qb[w * 128 + ut * 16 + ul];
    }
    __syncthreads();

    int v  = tid & 127;
    int ug = tid >> 7;
    const float4* ps4 = (const float4*)ps;
    const float4* qs4 = (const float4*)qs;

    float acc[8] = {0,0,0,0,0,0,0,0};
    int idx = 0;
#pragma unroll 4
    for (int w = 0; w < 128; ++w) {
        float cv = ct[idx], sv = st[idx];
        idx = (idx + v) & 127;
        float4 p0 = ps4[w * 4 + ug * 2 + 0];
        float4 p1 = ps4[w * 4 + ug * 2 + 1];
        float4 q0 = qs4[w * 4 + ug * 2 + 0];
        float4 q1 = qs4[w * 4 + ug * 2 + 1];
        acc[0] += cv * p0.x - sv * q0.x;
        acc[1] += cv * p0.y - sv * q0.y;
        acc[2] += cv * p0.z - sv * q0.z;
        acc[3] += cv * p0.w - sv * q0.w;
        acc[4] += cv * p1.x - sv * q1.x;
        acc[5] += cv * p1.y - sv * q1.y;
        acc[6] += cv * p1.z - sv * q1.z;
        acc[7] += cv * p1.w - sv * q1.w;
    }
    size_t base = (size_t)b * HW;
#pragma unroll
    for (int j = 0; j < 8; ++j) {
        int u = ut * 16 + ug * 8 + j;
        g_sf[base + u * 128 + v] = acc[j];   // coalesced in v
    }
}

// ---------------------------------------------------------------------------
// Kernel 4: out[b,c,h,w] = x[b,c,h,w] * (cf[b,c] + sf[b,h,w])
// ---------------------------------------------------------------------------
__global__ void out_kernel(const float4* __restrict__ x, float4* __restrict__ out) {
    int i = blockIdx.x * 256 + threadIdx.x;    // 0 .. 16777215
    int plane = i >> 12;                        // (b*256 + c)
    int pos = i & 4095;
    int b = plane >> 8;
    float cf = g_cf[plane];
    float4 f = ((const float4*)g_sf)[b * HW4 + pos];
    float4 v = x[i];
    float4 o;
    o.x = v.x * (cf + f.x);
    o.y = v.y * (cf + f.y);
    o.z = v.z * (cf + f.z);
    o.w = v.w * (cf + f.w);
    out[i] = o;
}

extern "C" void kernel_launch(void* const* d_in, const int* in_sizes, int n_in,
                              void* d_out, int out_size) {
    const float* x    = (const float*)d_in[0];   // [16,256,128,128]
    const float* Wm   = (const float*)d_in[1];   // [256,256]
    const float* bias = (const float*)d_in[2];   // [256]
    float* out = (float*)d_out;

    // cf path is independent of mean path; both feed the final pass.
    cf_kernel<<<B_, C_>>>(x, Wm, bias);
    mean_kernel<<<(B_ * HW4) / 256, 256>>>((const float4*)x);
    dft_stage1<<<dim3(8, B_), 256>>>();
    dft_stage2<<<dim3(8, B_), 256>>>();
    out_kernel<<<(B_ * C_ * HW4) / 256, 256>>>((const float4*)x, (float4*)out);
}